// round 2
// baseline (speedup 1.0000x reference)
#include <cuda_runtime.h>
#include <math.h>

#define N_NODES_C 100000
#define N_EDGES_C 524288
#define HDC 128
#define EPSC 1e-5f

// Per-node precomputed projections:
// T[n][  0:128] = x[n] @ W1[  0:128,:]   (src contribution to h)
// T[n][128:256] = x[n] @ W1[128:256,:]   (dst contribution to h)
// T[n][256:384] = x[n] @ Wg[  0:128,:]   (src contribution to gate)
// T[n][384:512] = x[n] @ Wg[128:256,:]   (dst contribution to gate)
static __device__ float g_T[(size_t)N_NODES_C * 512];

// ---------------------------------------------------------------------------
// Kernel 1: node projection GEMM.  32 nodes per block, 256 threads.
// ---------------------------------------------------------------------------
__global__ __launch_bounds__(256, 2)
void node_proj_kernel(const float* __restrict__ x,
                      const float* __restrict__ W1,
                      const float* __restrict__ Wg)
{
    extern __shared__ float smem[];
    float* sh_w  = smem;              // 128*128 = 16384 floats
    float* sh_xT = smem + 128 * 128;  // 128*36  =  4608 floats (x transposed, padded)

    const int tid   = threadIdx.x;
    const int node0 = blockIdx.x * 32;

    // Load x tile transposed: sh_xT[k][n]
    for (int i = tid; i < 32 * 32; i += 256) {
        int n  = i / 32;
        int c4 = i % 32;
        float4 v = *(const float4*)(x + (size_t)(node0 + n) * HDC + c4 * 4);
        int c = c4 * 4;
        sh_xT[(c + 0) * 36 + n] = v.x;
        sh_xT[(c + 1) * 36 + n] = v.y;
        sh_xT[(c + 2) * 36 + n] = v.z;
        sh_xT[(c + 3) * 36 + n] = v.w;
    }

    const int cg = tid & 31;
    const int ng = tid >> 5;
    const int c0 = cg * 4;
    const int n0 = ng * 4;

    for (int q = 0; q < 4; q++) {
        const float* Wsrc = (q < 2 ? W1 : Wg) + (size_t)(q & 1) * (128 * HDC);
        __syncthreads();   // covers sh_xT fill on q==0, and prior reads of sh_w otherwise
        for (int i = tid; i < 128 * 32; i += 256)
            *(float4*)(sh_w + (size_t)i * 4) = *(const float4*)(Wsrc + (size_t)i * 4);
        __syncthreads();

        float acc[4][4];
        #pragma unroll
        for (int a = 0; a < 4; a++)
            #pragma unroll
            for (int b = 0; b < 4; b++) acc[a][b] = 0.f;

        #pragma unroll 4
        for (int k = 0; k < 128; k++) {
            const float4 wv = *(const float4*)(sh_w  + k * 128 + c0);
            const float4 xv = *(const float4*)(sh_xT + k * 36  + n0);
            const float xa[4] = {xv.x, xv.y, xv.z, xv.w};
            const float wa[4] = {wv.x, wv.y, wv.z, wv.w};
            #pragma unroll
            for (int a = 0; a < 4; a++)
                #pragma unroll
                for (int b = 0; b < 4; b++)
                    acc[a][b] = fmaf(xa[a], wa[b], acc[a][b]);
        }

        #pragma unroll
        for (int a = 0; a < 4; a++) {
            float4 o = make_float4(acc[a][0], acc[a][1], acc[a][2], acc[a][3]);
            *(float4*)(g_T + (size_t)(node0 + n0 + a) * 512 + q * 128 + c0) = o;
        }
    }
}

// ---------------------------------------------------------------------------
// Kernel 2: fused edge kernel. 32 edges per block, 256 threads.
//   acc_h = b1 + T[src][0:128] + T[dst][128:256] + e @ W1[256:384,:]
//   acc_g = bg + T[src][256:384] + T[dst][384:512] + e @ Wg[256:384,:]
//   h = gelu(LN(acc_h; g1,be1)); h2 = h @ W2 + b2
//   out = LN(h2 * sigmoid(acc_g) + e; gn,bn)
// ---------------------------------------------------------------------------
__global__ __launch_bounds__(256, 1)
void edge_kernel(const int* __restrict__ edge_index,
                 const float* __restrict__ edge_attr,
                 const float* __restrict__ W1,
                 const float* __restrict__ b1,
                 const float* __restrict__ g1,
                 const float* __restrict__ be1,
                 const float* __restrict__ W2,
                 const float* __restrict__ b2,
                 const float* __restrict__ Wg,
                 const float* __restrict__ bg,
                 const float* __restrict__ gn,
                 const float* __restrict__ bn,
                 float* __restrict__ out)
{
    extern __shared__ float smem[];
    float* wA  = smem;            // 16384 floats (W1e, later W2)
    float* wB  = smem + 16384;    // 16384 floats (Wge)
    float* eT  = smem + 32768;    // 128*36 = 4608 floats (edge_attr transposed)
    float* hT  = smem + 37376;    // 128*36 = 4608 floats (gelu(LN(h)) transposed)
    float* red = smem + 41984;    // 32*132 = 4224 floats (LN staging)

    const int tid    = threadIdx.x;
    const int e0blk  = blockIdx.x * 32;
    const int cg     = tid & 31;
    const int eg     = tid >> 5;
    const int c0     = cg * 4;
    const int erow0  = eg * 4;
    const int lane   = tid & 31;
    const int wid    = tid >> 5;

    // --- Issue the random gathers early (latency overlapped with staging) ---
    float4 th_s[4], th_d[4], tg_s[4], tg_d[4];
    #pragma unroll
    for (int i = 0; i < 4; i++) {
        int e = e0blk + erow0 + i;
        int s = edge_index[e];
        int d = edge_index[N_EDGES_C + e];
        const float* Ts = g_T + (size_t)s * 512;
        const float* Td = g_T + (size_t)d * 512;
        th_s[i] = *(const float4*)(Ts + c0);
        th_d[i] = *(const float4*)(Td + 128 + c0);
        tg_s[i] = *(const float4*)(Ts + 256 + c0);
        tg_d[i] = *(const float4*)(Td + 384 + c0);
    }

    // --- Stage weights: W1 edge-part -> wA, Wg edge-part -> wB ---
    const float* W1e = W1 + 256 * HDC;
    const float* Wge = Wg + 256 * HDC;
    for (int i = tid; i < 128 * 32; i += 256) {
        *(float4*)(wA + (size_t)i * 4) = *(const float4*)(W1e + (size_t)i * 4);
        *(float4*)(wB + (size_t)i * 4) = *(const float4*)(Wge + (size_t)i * 4);
    }

    // --- Stage edge_attr tile transposed: eT[k][e] ---
    for (int i = tid; i < 32 * 32; i += 256) {
        int e  = i / 32;
        int c4 = i % 32;
        float4 v = *(const float4*)(edge_attr + (size_t)(e0blk + e) * HDC + c4 * 4);
        int c = c4 * 4;
        eT[(c + 0) * 36 + e] = v.x;
        eT[(c + 1) * 36 + e] = v.y;
        eT[(c + 2) * 36 + e] = v.z;
        eT[(c + 3) * 36 + e] = v.w;
    }

    const float4 b1v = *(const float4*)(b1 + c0);
    const float4 bgv = *(const float4*)(bg + c0);

    // --- Init accumulators with bias + gathered per-node projections ---
    float acc_h[4][4], acc_g[4][4];
    #pragma unroll
    for (int i = 0; i < 4; i++) {
        acc_h[i][0] = b1v.x + th_s[i].x + th_d[i].x;
        acc_h[i][1] = b1v.y + th_s[i].y + th_d[i].y;
        acc_h[i][2] = b1v.z + th_s[i].z + th_d[i].z;
        acc_h[i][3] = b1v.w + th_s[i].w + th_d[i].w;
        acc_g[i][0] = bgv.x + tg_s[i].x + tg_d[i].x;
        acc_g[i][1] = bgv.y + tg_s[i].y + tg_d[i].y;
        acc_g[i][2] = bgv.z + tg_s[i].z + tg_d[i].z;
        acc_g[i][3] = bgv.w + tg_s[i].w + tg_d[i].w;
    }

    __syncthreads();

    // --- GEMM1: e @ W1e and e @ Wge simultaneously (shared e loads) ---
    #pragma unroll 4
    for (int k = 0; k < 128; k++) {
        const float4 w1v = *(const float4*)(wA + k * 128 + c0);
        const float4 wgv = *(const float4*)(wB + k * 128 + c0);
        const float4 ev  = *(const float4*)(eT + k * 36 + erow0);
        const float eak[4] = {ev.x, ev.y, ev.z, ev.w};
        const float w1a[4] = {w1v.x, w1v.y, w1v.z, w1v.w};
        const float wga[4] = {wgv.x, wgv.y, wgv.z, wgv.w};
        #pragma unroll
        for (int i = 0; i < 4; i++)
            #pragma unroll
            for (int j = 0; j < 4; j++) {
                acc_h[i][j] = fmaf(eak[i], w1a[j], acc_h[i][j]);
                acc_g[i][j] = fmaf(eak[i], wga[j], acc_g[i][j]);
            }
    }

    // --- Stage h for LayerNorm ---
    #pragma unroll
    for (int i = 0; i < 4; i++)
        *(float4*)(red + (erow0 + i) * 132 + c0) =
            make_float4(acc_h[i][0], acc_h[i][1], acc_h[i][2], acc_h[i][3]);
    __syncthreads();

    // --- Load W2 into wA (GEMM1 done reading it) ---
    for (int i = tid; i < 128 * 32; i += 256)
        *(float4*)(wA + (size_t)i * 4) = *(const float4*)(W2 + (size_t)i * 4);

    // --- LayerNorm(h) + GELU; each warp handles 4 edges; write transposed ---
    {
        const float4 g1v  = *(const float4*)(g1  + lane * 4);
        const float4 be1v = *(const float4*)(be1 + lane * 4);
        const float ga[4]  = {g1v.x, g1v.y, g1v.z, g1v.w};
        const float ba[4]  = {be1v.x, be1v.y, be1v.z, be1v.w};
        #pragma unroll
        for (int ii = 0; ii < 4; ii++) {
            int e = wid * 4 + ii;
            float4 v = *(const float4*)(red + e * 132 + lane * 4);
            float s  = v.x + v.y + v.z + v.w;
            float ss = v.x * v.x + v.y * v.y + v.z * v.z + v.w * v.w;
            #pragma unroll
            for (int o = 16; o > 0; o >>= 1) {
                s  += __shfl_xor_sync(0xFFFFFFFFu, s,  o);
                ss += __shfl_xor_sync(0xFFFFFFFFu, ss, o);
            }
            float mu   = s * (1.0f / 128.0f);
            float var  = ss * (1.0f / 128.0f) - mu * mu;
            float rstd = rsqrtf(var + EPSC);
            const float vals[4] = {v.x, v.y, v.z, v.w};
            #pragma unroll
            for (int j = 0; j < 4; j++) {
                int c = lane * 4 + j;
                float y  = (vals[j] - mu) * rstd * ga[j] + ba[j];
                float gl = 0.5f * y * (1.0f + erff(y * 0.70710678118654752440f));
                hT[c * 36 + e] = gl;
            }
        }
    }
    __syncthreads();

    // --- GEMM2: h @ W2 + b2 ---
    const float4 b2v = *(const float4*)(b2 + c0);
    float acc2[4][4];
    #pragma unroll
    for (int i = 0; i < 4; i++) {
        acc2[i][0] = b2v.x; acc2[i][1] = b2v.y; acc2[i][2] = b2v.z; acc2[i][3] = b2v.w;
    }
    #pragma unroll 4
    for (int k = 0; k < 128; k++) {
        const float4 wv = *(const float4*)(wA + k * 128 + c0);
        const float4 hv = *(const float4*)(hT + k * 36 + erow0);
        const float ha[4] = {hv.x, hv.y, hv.z, hv.w};
        const float wa[4] = {wv.x, wv.y, wv.z, wv.w};
        #pragma unroll
        for (int i = 0; i < 4; i++)
            #pragma unroll
            for (int j = 0; j < 4; j++)
                acc2[i][j] = fmaf(ha[i], wa[j], acc2[i][j]);
    }

    // --- Combine: r = h2 * sigmoid(g_pre) + edge_attr; stage for final LN ---
    #pragma unroll
    for (int i = 0; i < 4; i++) {
        float rr[4];
        #pragma unroll
        for (int j = 0; j < 4; j++) {
            float gate = 1.0f / (1.0f + expf(-acc_g[i][j]));
            float eav  = eT[(c0 + j) * 36 + (erow0 + i)];
            rr[j] = acc2[i][j] * gate + eav;
        }
        *(float4*)(red + (erow0 + i) * 132 + c0) = make_float4(rr[0], rr[1], rr[2], rr[3]);
    }
    __syncthreads();

    // --- Final LayerNorm, write output coalesced ---
    {
        const float4 gnv = *(const float4*)(gn + lane * 4);
        const float4 bnv = *(const float4*)(bn + lane * 4);
        const float ga[4] = {gnv.x, gnv.y, gnv.z, gnv.w};
        const float ba[4] = {bnv.x, bnv.y, bnv.z, bnv.w};
        #pragma unroll
        for (int ii = 0; ii < 4; ii++) {
            int e = wid * 4 + ii;
            float4 v = *(const float4*)(red + e * 132 + lane * 4);
            float s  = v.x + v.y + v.z + v.w;
            float ss = v.x * v.x + v.y * v.y + v.z * v.z + v.w * v.w;
            #pragma unroll
            for (int o = 16; o > 0; o >>= 1) {
                s  += __shfl_xor_sync(0xFFFFFFFFu, s,  o);
                ss += __shfl_xor_sync(0xFFFFFFFFu, ss, o);
            }
            float mu   = s * (1.0f / 128.0f);
            float var  = ss * (1.0f / 128.0f) - mu * mu;
            float rstd = rsqrtf(var + EPSC);
            const float vals[4] = {v.x, v.y, v.z, v.w};
            float4 o4;
            o4.x = (vals[0] - mu) * rstd * ga[0] + ba[0];
            o4.y = (vals[1] - mu) * rstd * ga[1] + ba[1];
            o4.z = (vals[2] - mu) * rstd * ga[2] + ba[2];
            o4.w = (vals[3] - mu) * rstd * ga[3] + ba[3];
            *(float4*)(out + (size_t)(e0blk + e) * HDC + lane * 4) = o4;
        }
    }
}

// ---------------------------------------------------------------------------
extern "C" void kernel_launch(void* const* d_in, const int* in_sizes, int n_in,
                              void* d_out, int out_size)
{
    const float* x   = (const float*)d_in[0];
    const int*   ei  = (const int*)d_in[1];
    const float* ea  = (const float*)d_in[2];
    const float* W1  = (const float*)d_in[3];
    const float* b1  = (const float*)d_in[4];
    const float* g1  = (const float*)d_in[5];
    const float* be1 = (const float*)d_in[6];
    const float* W2  = (const float*)d_in[7];
    const float* b2  = (const float*)d_in[8];
    const float* Wg  = (const float*)d_in[9];
    const float* bg  = (const float*)d_in[10];
    const float* gn  = (const float*)d_in[11];
    const float* bn  = (const float*)d_in[12];
    float*       out = (float*)d_out;

    const int node_smem = (128 * 128 + 128 * 36) * 4;                       // 83968 B
    const int edge_smem = (16384 + 16384 + 4608 + 4608 + 32 * 132) * 4;     // 184832 B
    cudaFuncSetAttribute(node_proj_kernel,
                         cudaFuncAttributeMaxDynamicSharedMemorySize, node_smem);
    cudaFuncSetAttribute(edge_kernel,
                         cudaFuncAttributeMaxDynamicSharedMemorySize, edge_smem);

    node_proj_kernel<<<N_NODES_C / 32, 256, node_smem>>>(x, W1, Wg);
    edge_kernel<<<N_EDGES_C / 32, 256, edge_smem>>>(ei, ea, W1, b1, g1, be1,
                                                    W2, b2, Wg, bg, gn, bn, out);
}

// round 3
// speedup vs baseline: 1.0006x; 1.0006x over previous
#include <cuda_runtime.h>
#include <math.h>

#define N_NODES_C 100000
#define N_EDGES_C 524288
#define HDC 128
#define EPSC 1e-5f

// Per-node precomputed projections:
// T[n][  0:128] = x[n] @ W1[  0:128,:]   (src contribution to h)
// T[n][128:256] = x[n] @ W1[128:256,:]   (dst contribution to h)
// T[n][256:384] = x[n] @ Wg[  0:128,:]   (src contribution to gate)
// T[n][384:512] = x[n] @ Wg[128:256,:]   (dst contribution to gate)
static __device__ float g_T[(size_t)N_NODES_C * 512];

// ---------------------------------------------------------------------------
// Kernel 1: node projection GEMM.  32 nodes per block, 256 threads.
// ---------------------------------------------------------------------------
__global__ __launch_bounds__(256, 2)
void node_proj_kernel(const float* __restrict__ x,
                      const float* __restrict__ W1,
                      const float* __restrict__ Wg)
{
    extern __shared__ float smem[];
    float* sh_w  = smem;              // 128*128 = 16384 floats
    float* sh_xT = smem + 128 * 128;  // 128*36  =  4608 floats (x transposed, padded)

    const int tid   = threadIdx.x;
    const int node0 = blockIdx.x * 32;

    // Load x tile transposed: sh_xT[k][n]
    for (int i = tid; i < 32 * 32; i += 256) {
        int n  = i / 32;
        int c4 = i % 32;
        float4 v = *(const float4*)(x + (size_t)(node0 + n) * HDC + c4 * 4);
        int c = c4 * 4;
        sh_xT[(c + 0) * 36 + n] = v.x;
        sh_xT[(c + 1) * 36 + n] = v.y;
        sh_xT[(c + 2) * 36 + n] = v.z;
        sh_xT[(c + 3) * 36 + n] = v.w;
    }

    const int cg = tid & 31;
    const int ng = tid >> 5;
    const int c0 = cg * 4;
    const int n0 = ng * 4;

    for (int q = 0; q < 4; q++) {
        const float* Wsrc = (q < 2 ? W1 : Wg) + (size_t)(q & 1) * (128 * HDC);
        __syncthreads();   // covers sh_xT fill on q==0, and prior reads of sh_w otherwise
        for (int i = tid; i < 128 * 32; i += 256)
            *(float4*)(sh_w + (size_t)i * 4) = *(const float4*)(Wsrc + (size_t)i * 4);
        __syncthreads();

        float acc[4][4];
        #pragma unroll
        for (int a = 0; a < 4; a++)
            #pragma unroll
            for (int b = 0; b < 4; b++) acc[a][b] = 0.f;

        #pragma unroll 4
        for (int k = 0; k < 128; k++) {
            const float4 wv = *(const float4*)(sh_w  + k * 128 + c0);
            const float4 xv = *(const float4*)(sh_xT + k * 36  + n0);
            const float xa[4] = {xv.x, xv.y, xv.z, xv.w};
            const float wa[4] = {wv.x, wv.y, wv.z, wv.w};
            #pragma unroll
            for (int a = 0; a < 4; a++)
                #pragma unroll
                for (int b = 0; b < 4; b++)
                    acc[a][b] = fmaf(xa[a], wa[b], acc[a][b]);
        }

        #pragma unroll
        for (int a = 0; a < 4; a++) {
            float4 o = make_float4(acc[a][0], acc[a][1], acc[a][2], acc[a][3]);
            *(float4*)(g_T + (size_t)(node0 + n0 + a) * 512 + q * 128 + c0) = o;
        }
    }
}

// ---------------------------------------------------------------------------
// Kernel 2: fused edge kernel. 32 edges per block, 256 threads.
//   acc_h = b1 + T[src][0:128] + T[dst][128:256] + e @ W1[256:384,:]
//   acc_g = bg + T[src][256:384] + T[dst][384:512] + e @ Wg[256:384,:]
//   h = gelu(LN(acc_h; g1,be1)); h2 = h @ W2 + b2
//   out = LN(h2 * sigmoid(acc_g) + e; gn,bn)
// ---------------------------------------------------------------------------
__global__ __launch_bounds__(256, 1)
void edge_kernel(const int* __restrict__ edge_index,
                 const float* __restrict__ edge_attr,
                 const float* __restrict__ W1,
                 const float* __restrict__ b1,
                 const float* __restrict__ g1,
                 const float* __restrict__ be1,
                 const float* __restrict__ W2,
                 const float* __restrict__ b2,
                 const float* __restrict__ Wg,
                 const float* __restrict__ bg,
                 const float* __restrict__ gn,
                 const float* __restrict__ bn,
                 float* __restrict__ out)
{
    extern __shared__ float smem[];
    float* wA  = smem;            // 16384 floats (W1e, later W2)
    float* wB  = smem + 16384;    // 16384 floats (Wge)
    float* eT  = smem + 32768;    // 128*36 = 4608 floats (edge_attr transposed)
    float* hT  = smem + 37376;    // 128*36 = 4608 floats (gelu(LN(h)) transposed)
    float* red = smem + 41984;    // 32*132 = 4224 floats (LN staging)

    const int tid    = threadIdx.x;
    const int e0blk  = blockIdx.x * 32;
    const int cg     = tid & 31;
    const int eg     = tid >> 5;
    const int c0     = cg * 4;
    const int erow0  = eg * 4;
    const int lane   = tid & 31;
    const int wid    = tid >> 5;

    // --- Issue the random gathers early (latency overlapped with staging) ---
    float4 th_s[4], th_d[4], tg_s[4], tg_d[4];
    #pragma unroll
    for (int i = 0; i < 4; i++) {
        int e = e0blk + erow0 + i;
        int s = edge_index[e];
        int d = edge_index[N_EDGES_C + e];
        const float* Ts = g_T + (size_t)s * 512;
        const float* Td = g_T + (size_t)d * 512;
        th_s[i] = *(const float4*)(Ts + c0);
        th_d[i] = *(const float4*)(Td + 128 + c0);
        tg_s[i] = *(const float4*)(Ts + 256 + c0);
        tg_d[i] = *(const float4*)(Td + 384 + c0);
    }

    // --- Stage weights: W1 edge-part -> wA, Wg edge-part -> wB ---
    const float* W1e = W1 + 256 * HDC;
    const float* Wge = Wg + 256 * HDC;
    for (int i = tid; i < 128 * 32; i += 256) {
        *(float4*)(wA + (size_t)i * 4) = *(const float4*)(W1e + (size_t)i * 4);
        *(float4*)(wB + (size_t)i * 4) = *(const float4*)(Wge + (size_t)i * 4);
    }

    // --- Stage edge_attr tile transposed: eT[k][e] ---
    for (int i = tid; i < 32 * 32; i += 256) {
        int e  = i / 32;
        int c4 = i % 32;
        float4 v = *(const float4*)(edge_attr + (size_t)(e0blk + e) * HDC + c4 * 4);
        int c = c4 * 4;
        eT[(c + 0) * 36 + e] = v.x;
        eT[(c + 1) * 36 + e] = v.y;
        eT[(c + 2) * 36 + e] = v.z;
        eT[(c + 3) * 36 + e] = v.w;
    }

    const float4 b1v = *(const float4*)(b1 + c0);
    const float4 bgv = *(const float4*)(bg + c0);

    // --- Init accumulators with bias + gathered per-node projections ---
    float acc_h[4][4], acc_g[4][4];
    #pragma unroll
    for (int i = 0; i < 4; i++) {
        acc_h[i][0] = b1v.x + th_s[i].x + th_d[i].x;
        acc_h[i][1] = b1v.y + th_s[i].y + th_d[i].y;
        acc_h[i][2] = b1v.z + th_s[i].z + th_d[i].z;
        acc_h[i][3] = b1v.w + th_s[i].w + th_d[i].w;
        acc_g[i][0] = bgv.x + tg_s[i].x + tg_d[i].x;
        acc_g[i][1] = bgv.y + tg_s[i].y + tg_d[i].y;
        acc_g[i][2] = bgv.z + tg_s[i].z + tg_d[i].z;
        acc_g[i][3] = bgv.w + tg_s[i].w + tg_d[i].w;
    }

    __syncthreads();

    // --- GEMM1: e @ W1e and e @ Wge simultaneously (shared e loads) ---
    #pragma unroll 4
    for (int k = 0; k < 128; k++) {
        const float4 w1v = *(const float4*)(wA + k * 128 + c0);
        const float4 wgv = *(const float4*)(wB + k * 128 + c0);
        const float4 ev  = *(const float4*)(eT + k * 36 + erow0);
        const float eak[4] = {ev.x, ev.y, ev.z, ev.w};
        const float w1a[4] = {w1v.x, w1v.y, w1v.z, w1v.w};
        const float wga[4] = {wgv.x, wgv.y, wgv.z, wgv.w};
        #pragma unroll
        for (int i = 0; i < 4; i++)
            #pragma unroll
            for (int j = 0; j < 4; j++) {
                acc_h[i][j] = fmaf(eak[i], w1a[j], acc_h[i][j]);
                acc_g[i][j] = fmaf(eak[i], wga[j], acc_g[i][j]);
            }
    }

    // --- Stage h for LayerNorm ---
    #pragma unroll
    for (int i = 0; i < 4; i++)
        *(float4*)(red + (erow0 + i) * 132 + c0) =
            make_float4(acc_h[i][0], acc_h[i][1], acc_h[i][2], acc_h[i][3]);
    __syncthreads();

    // --- Load W2 into wA (GEMM1 done reading it) ---
    for (int i = tid; i < 128 * 32; i += 256)
        *(float4*)(wA + (size_t)i * 4) = *(const float4*)(W2 + (size_t)i * 4);

    // --- LayerNorm(h) + GELU; each warp handles 4 edges; write transposed ---
    {
        const float4 g1v  = *(const float4*)(g1  + lane * 4);
        const float4 be1v = *(const float4*)(be1 + lane * 4);
        const float ga[4]  = {g1v.x, g1v.y, g1v.z, g1v.w};
        const float ba[4]  = {be1v.x, be1v.y, be1v.z, be1v.w};
        #pragma unroll
        for (int ii = 0; ii < 4; ii++) {
            int e = wid * 4 + ii;
            float4 v = *(const float4*)(red + e * 132 + lane * 4);
            float s  = v.x + v.y + v.z + v.w;
            float ss = v.x * v.x + v.y * v.y + v.z * v.z + v.w * v.w;
            #pragma unroll
            for (int o = 16; o > 0; o >>= 1) {
                s  += __shfl_xor_sync(0xFFFFFFFFu, s,  o);
                ss += __shfl_xor_sync(0xFFFFFFFFu, ss, o);
            }
            float mu   = s * (1.0f / 128.0f);
            float var  = ss * (1.0f / 128.0f) - mu * mu;
            float rstd = rsqrtf(var + EPSC);
            const float vals[4] = {v.x, v.y, v.z, v.w};
            #pragma unroll
            for (int j = 0; j < 4; j++) {
                int c = lane * 4 + j;
                float y  = (vals[j] - mu) * rstd * ga[j] + ba[j];
                float gl = 0.5f * y * (1.0f + erff(y * 0.70710678118654752440f));
                hT[c * 36 + e] = gl;
            }
        }
    }
    __syncthreads();

    // --- GEMM2: h @ W2 + b2 ---
    const float4 b2v = *(const float4*)(b2 + c0);
    float acc2[4][4];
    #pragma unroll
    for (int i = 0; i < 4; i++) {
        acc2[i][0] = b2v.x; acc2[i][1] = b2v.y; acc2[i][2] = b2v.z; acc2[i][3] = b2v.w;
    }
    #pragma unroll 4
    for (int k = 0; k < 128; k++) {
        const float4 wv = *(const float4*)(wA + k * 128 + c0);
        const float4 hv = *(const float4*)(hT + k * 36 + erow0);
        const float ha[4] = {hv.x, hv.y, hv.z, hv.w};
        const float wa[4] = {wv.x, wv.y, wv.z, wv.w};
        #pragma unroll
        for (int i = 0; i < 4; i++)
            #pragma unroll
            for (int j = 0; j < 4; j++)
                acc2[i][j] = fmaf(ha[i], wa[j], acc2[i][j]);
    }

    // --- Combine: r = h2 * sigmoid(g_pre) + edge_attr; stage for final LN ---
    #pragma unroll
    for (int i = 0; i < 4; i++) {
        float rr[4];
        #pragma unroll
        for (int j = 0; j < 4; j++) {
            float gate = 1.0f / (1.0f + expf(-acc_g[i][j]));
            float eav  = eT[(c0 + j) * 36 + (erow0 + i)];
            rr[j] = acc2[i][j] * gate + eav;
        }
        *(float4*)(red + (erow0 + i) * 132 + c0) = make_float4(rr[0], rr[1], rr[2], rr[3]);
    }
    __syncthreads();

    // --- Final LayerNorm, write output coalesced ---
    {
        const float4 gnv = *(const float4*)(gn + lane * 4);
        const float4 bnv = *(const float4*)(bn + lane * 4);
        const float ga[4] = {gnv.x, gnv.y, gnv.z, gnv.w};
        const float ba[4] = {bnv.x, bnv.y, bnv.z, bnv.w};
        #pragma unroll
        for (int ii = 0; ii < 4; ii++) {
            int e = wid * 4 + ii;
            float4 v = *(const float4*)(red + e * 132 + lane * 4);
            float s  = v.x + v.y + v.z + v.w;
            float ss = v.x * v.x + v.y * v.y + v.z * v.z + v.w * v.w;
            #pragma unroll
            for (int o = 16; o > 0; o >>= 1) {
                s  += __shfl_xor_sync(0xFFFFFFFFu, s,  o);
                ss += __shfl_xor_sync(0xFFFFFFFFu, ss, o);
            }
            float mu   = s * (1.0f / 128.0f);
            float var  = ss * (1.0f / 128.0f) - mu * mu;
            float rstd = rsqrtf(var + EPSC);
            const float vals[4] = {v.x, v.y, v.z, v.w};
            float4 o4;
            o4.x = (vals[0] - mu) * rstd * ga[0] + ba[0];
            o4.y = (vals[1] - mu) * rstd * ga[1] + ba[1];
            o4.z = (vals[2] - mu) * rstd * ga[2] + ba[2];
            o4.w = (vals[3] - mu) * rstd * ga[3] + ba[3];
            *(float4*)(out + (size_t)(e0blk + e) * HDC + lane * 4) = o4;
        }
    }
}

// ---------------------------------------------------------------------------
extern "C" void kernel_launch(void* const* d_in, const int* in_sizes, int n_in,
                              void* d_out, int out_size)
{
    const float* x   = (const float*)d_in[0];
    const int*   ei  = (const int*)d_in[1];
    const float* ea  = (const float*)d_in[2];
    const float* W1  = (const float*)d_in[3];
    const float* b1  = (const float*)d_in[4];
    const float* g1  = (const float*)d_in[5];
    const float* be1 = (const float*)d_in[6];
    const float* W2  = (const float*)d_in[7];
    const float* b2  = (const float*)d_in[8];
    const float* Wg  = (const float*)d_in[9];
    const float* bg  = (const float*)d_in[10];
    const float* gn  = (const float*)d_in[11];
    const float* bn  = (const float*)d_in[12];
    float*       out = (float*)d_out;

    const int node_smem = (128 * 128 + 128 * 36) * 4;                       // 83968 B
    const int edge_smem = (16384 + 16384 + 4608 + 4608 + 32 * 132) * 4;     // 184832 B
    cudaFuncSetAttribute(node_proj_kernel,
                         cudaFuncAttributeMaxDynamicSharedMemorySize, node_smem);
    cudaFuncSetAttribute(edge_kernel,
                         cudaFuncAttributeMaxDynamicSharedMemorySize, edge_smem);

    node_proj_kernel<<<N_NODES_C / 32, 256, node_smem>>>(x, W1, Wg);
    edge_kernel<<<N_EDGES_C / 32, 256, edge_smem>>>(ei, ea, W1, b1, g1, be1,
                                                    W2, b2, Wg, bg, gn, bn, out);
}

// round 5
// speedup vs baseline: 2.2176x; 2.2163x over previous
#include <cuda_runtime.h>
#include <cuda_bf16.h>
#include <stdint.h>
#include <math.h>

#define NN 100000
#define NE 524288
#define EPSC 1e-5f
#define EDGE_TILES 4096
#define NODE_TILES 782
#define GRID_P 148
#define SQRT1_2 0.70710678118654752440f

// g_T[n][0:128]=x@W1[0:128]  [128:256]=x@W1[128:256]  [256:384]=x@Wg[0:128]  [384:512]=x@Wg[128:256]
static __device__ float g_T[(size_t)NN * 512];

// ---------------- helpers ----------------
// swizzled byte offset inside a [row][128 bf16 = 256B] smem matrix
__device__ __forceinline__ int swb(int row, int b) {
    return row * 256 + (b ^ ((row & 7) << 4));
}
__device__ __forceinline__ void split_pack(float a, float b, uint32_t& hi, uint32_t& lo) {
    __nv_bfloat16 ha = __float2bfloat16(a), hb = __float2bfloat16(b);
    __nv_bfloat162 h2 = __halves2bfloat162(ha, hb);
    hi = *reinterpret_cast<uint32_t*>(&h2);
    __nv_bfloat162 l2 = __floats2bfloat162_rn(a - __bfloat162float(ha), b - __bfloat162float(hb));
    lo = *reinterpret_cast<uint32_t*>(&l2);
}
__device__ __forceinline__ void mma16816(float* c, uint32_t a0, uint32_t a1, uint32_t a2,
                                         uint32_t a3, uint32_t b0, uint32_t b1) {
    asm volatile("mma.sync.aligned.m16n8k16.row.col.f32.bf16.bf16.f32 "
                 "{%0,%1,%2,%3}, {%4,%5,%6,%7}, {%8,%9}, {%0,%1,%2,%3};"
                 : "+f"(c[0]), "+f"(c[1]), "+f"(c[2]), "+f"(c[3])
                 : "r"(a0), "r"(a1), "r"(a2), "r"(a3), "r"(b0), "r"(b1));
}
// 3-term bf16-split mma against B row n, k-chunk offset o0 = 32*s + 4*t
__device__ __forceinline__ void mma3(float* acc, const uint32_t ah[4], const uint32_t al[4],
                                     const char* BH, const char* BL, int n, int o0) {
    uint32_t bh0 = *(const uint32_t*)(BH + swb(n, o0));
    uint32_t bh1 = *(const uint32_t*)(BH + swb(n, o0 + 16));
    uint32_t bl0 = *(const uint32_t*)(BL + swb(n, o0));
    uint32_t bl1 = *(const uint32_t*)(BL + swb(n, o0 + 16));
    mma16816(acc, ah[0], ah[1], ah[2], ah[3], bh0, bh1);
    mma16816(acc, al[0], al[1], al[2], al[3], bh0, bh1);
    mma16816(acc, ah[0], ah[1], ah[2], ah[3], bl0, bl1);
}
__device__ __forceinline__ void load_afrag(uint32_t f[4], const char* base, int lr, int o0) {
    f[0] = *(const uint32_t*)(base + swb(lr, o0));
    f[1] = *(const uint32_t*)(base + swb(lr + 8, o0));
    f[2] = *(const uint32_t*)(base + swb(lr, o0 + 16));
    f[3] = *(const uint32_t*)(base + swb(lr + 8, o0 + 16));
}

// ============================================================================
// Node kernel: g_T = x @ [W1 halves] then x @ [Wg halves]. Persistent.
// smem: BH 65536 | BL 65536 | AH 16384 | AL 16384 = 163840
// ============================================================================
__global__ __launch_bounds__(256, 1)
void node_mma_kernel(const float* __restrict__ x,
                     const float* __restrict__ W1,
                     const float* __restrict__ Wg)
{
    extern __shared__ char sm[];
    char* BH = sm;
    char* BL = sm + 65536;
    char* AH = sm + 131072;
    char* AL = sm + 147456;

    const int tid = threadIdx.x;
    const int w = tid >> 5, lane = tid & 31;
    const int g = lane >> 2, t = lane & 3;
    const int lr = (w & 3) * 16 + g;

    for (int q = 0; q < 2; q++) {
        const float* W = q ? Wg : W1;
        __syncthreads();
        // stage B: n<128 -> W[k][n] ; n>=128 -> W[128+k][n-128]   (256n x 128k)
        for (int i = tid; i < 8192; i += 256) {
            int n4 = i >> 7, k = i & 127;
            const float* src = (n4 < 32) ? (W + (size_t)k * 128 + n4 * 4)
                                         : (W + (size_t)(128 + k) * 128 + (n4 - 32) * 4);
            float4 v = *(const float4*)src;
            float vv[4] = {v.x, v.y, v.z, v.w};
            #pragma unroll
            for (int u = 0; u < 4; u++) {
                int n = n4 * 4 + u;
                __nv_bfloat16 h = __float2bfloat16(vv[u]);
                __nv_bfloat16 l = __float2bfloat16(vv[u] - __bfloat162float(h));
                int o = swb(n, 2 * k);
                *(__nv_bfloat16*)(BH + o) = h;
                *(__nv_bfloat16*)(BL + o) = l;
            }
        }
        __syncthreads();

        for (int tile = blockIdx.x; tile < NODE_TILES; tile += gridDim.x) {
            uint32_t a1h[8][4], a1l[8][4];
            #pragma unroll
            for (int half = 0; half < 2; half++) {
                __syncthreads();
                for (int i = tid; i < 2048; i += 256) {  // 64 rows x 32 float4
                    int r = i >> 5, c4 = i & 31;
                    int node = tile * 128 + half * 64 + r;
                    float4 v = (node < NN) ? *(const float4*)(x + (size_t)node * 128 + c4 * 4)
                                           : make_float4(0.f, 0.f, 0.f, 0.f);
                    uint32_t h0, l0, h1, l1;
                    split_pack(v.x, v.y, h0, l0);
                    split_pack(v.z, v.w, h1, l1);
                    int o = swb(r, 8 * c4);
                    *(uint32_t*)(AH + o) = h0; *(uint32_t*)(AH + o + 4) = h1;
                    *(uint32_t*)(AL + o) = l0; *(uint32_t*)(AL + o + 4) = l1;
                }
                __syncthreads();
                if ((w >> 2) == half) {
                    #pragma unroll
                    for (int s = 0; s < 8; s++) {
                        load_afrag(a1h[s], AH, lr, 32 * s + 4 * t);
                        load_afrag(a1l[s], AL, lr, 32 * s + 4 * t);
                    }
                }
            }

            const int n1 = tile * 128 + w * 16 + g;
            const int n2 = n1 + 8;
            #pragma unroll
            for (int nh = 0; nh < 2; nh++) {
                float acc[16][4];
                #pragma unroll
                for (int j = 0; j < 16; j++)
                    #pragma unroll
                    for (int c = 0; c < 4; c++) acc[j][c] = 0.f;
                #pragma unroll
                for (int s = 0; s < 8; s++) {
                    int o0 = 32 * s + 4 * t;
                    #pragma unroll
                    for (int j = 0; j < 16; j++)
                        mma3(acc[j], a1h[s], a1l[s], BH, BL, nh * 128 + j * 8 + g, o0);
                }
                float* base1 = g_T + (size_t)n1 * 512 + q * 256 + nh * 128;
                float* base2 = g_T + (size_t)n2 * 512 + q * 256 + nh * 128;
                #pragma unroll
                for (int j = 0; j < 16; j++) {
                    int col = j * 8 + 2 * t;
                    if (n1 < NN) *(float2*)(base1 + col) = make_float2(acc[j][0], acc[j][1]);
                    if (n2 < NN) *(float2*)(base2 + col) = make_float2(acc[j][2], acc[j][3]);
                }
            }
        }
    }
}

// ============================================================================
// Edge kernel: persistent, 128 edges/tile, 8 warps x 16 rows.
// smem: B1H 65536 | B1L 65536 | W2H 32768 | W2L 32768 | AH 16384 | AL 16384 = 229376
// ============================================================================
__global__ __launch_bounds__(256, 1)
void edge_mma_kernel(const int* __restrict__ ei, const float* __restrict__ ea,
                     const float* __restrict__ W1, const float* __restrict__ b1,
                     const float* __restrict__ g1, const float* __restrict__ be1,
                     const float* __restrict__ W2, const float* __restrict__ b2,
                     const float* __restrict__ Wg, const float* __restrict__ bg,
                     const float* __restrict__ gn, const float* __restrict__ bn,
                     float* __restrict__ out)
{
    extern __shared__ char sm[];
    char* B1H = sm;
    char* B1L = sm + 65536;
    char* W2H = sm + 131072;
    char* W2L = sm + 163840;
    char* AH  = sm + 196608;
    char* AL  = sm + 212992;

    const int tid = threadIdx.x;
    const int w = tid >> 5, lane = tid & 31;
    const int g = lane >> 2, t = lane & 3;
    const int lr = (w & 3) * 16 + g;

    // stage B1 = [W1e | Wge] (256n x 128k), edge-attr rows 256..383 of W1/Wg
    for (int i = tid; i < 8192; i += 256) {
        int n4 = i >> 7, k = i & 127;
        const float* src = (n4 < 32) ? (W1 + (size_t)(256 + k) * 128 + n4 * 4)
                                     : (Wg + (size_t)(256 + k) * 128 + (n4 - 32) * 4);
        float4 v = *(const float4*)src;
        float vv[4] = {v.x, v.y, v.z, v.w};
        #pragma unroll
        for (int u = 0; u < 4; u++) {
            int n = n4 * 4 + u;
            __nv_bfloat16 h = __float2bfloat16(vv[u]);
            __nv_bfloat16 l = __float2bfloat16(vv[u] - __bfloat162float(h));
            int o = swb(n, 2 * k);
            *(__nv_bfloat16*)(B1H + o) = h;
            *(__nv_bfloat16*)(B1L + o) = l;
        }
    }
    // stage W2 (128n x 128k)
    for (int i = tid; i < 4096; i += 256) {
        int n4 = i >> 7, k = i & 127;
        float4 v = *(const float4*)(W2 + (size_t)k * 128 + n4 * 4);
        float vv[4] = {v.x, v.y, v.z, v.w};
        #pragma unroll
        for (int u = 0; u < 4; u++) {
            int n = n4 * 4 + u;
            __nv_bfloat16 h = __float2bfloat16(vv[u]);
            __nv_bfloat16 l = __float2bfloat16(vv[u] - __bfloat162float(h));
            int o = swb(n, 2 * k);
            *(__nv_bfloat16*)(W2H + o) = h;
            *(__nv_bfloat16*)(W2L + o) = l;
        }
    }

    for (int tile = blockIdx.x; tile < EDGE_TILES; tile += gridDim.x) {
        // ---- stage A (edge_attr, bf16 hi/lo) in two 64-row passes; A1 frags -> regs ----
        uint32_t a1h[8][4], a1l[8][4];
        #pragma unroll
        for (int half = 0; half < 2; half++) {
            __syncthreads();
            for (int i = tid; i < 2048; i += 256) {
                int r = i >> 5, c4 = i & 31;
                int e = tile * 128 + half * 64 + r;
                float4 v = *(const float4*)(ea + (size_t)e * 128 + c4 * 4);
                uint32_t h0, l0, h1, l1;
                split_pack(v.x, v.y, h0, l0);
                split_pack(v.z, v.w, h1, l1);
                int o = swb(r, 8 * c4);
                *(uint32_t*)(AH + o) = h0; *(uint32_t*)(AH + o + 4) = h1;
                *(uint32_t*)(AL + o) = l0; *(uint32_t*)(AL + o + 4) = l1;
            }
            __syncthreads();
            if ((w >> 2) == half) {
                #pragma unroll
                for (int s = 0; s < 8; s++) {
                    load_afrag(a1h[s], AH, lr, 32 * s + 4 * t);
                    load_afrag(a1l[s], AL, lr, 32 * s + 4 * t);
                }
            }
        }

        // ---- gathers + biases init the accumulators (fp32 exact) ----
        const int e1 = tile * 128 + w * 16 + g;
        const int e2 = e1 + 8;
        const int is1 = ei[e1], id1 = ei[NE + e1];
        const int is2 = ei[e2], id2 = ei[NE + e2];
        const float* T1s = g_T + (size_t)is1 * 512;
        const float* T1d = g_T + (size_t)id1 * 512;
        const float* T2s = g_T + (size_t)is2 * 512;
        const float* T2d = g_T + (size_t)id2 * 512;

        float acc_h[16][4], acc_g[16][4];
        #pragma unroll
        for (int j = 0; j < 16; j++) {
            int col = j * 8 + 2 * t;
            float2 bb = *(const float2*)(b1 + col);
            float2 p1 = *(const float2*)(T1s + col);
            float2 q1 = *(const float2*)(T1d + 128 + col);
            float2 p2 = *(const float2*)(T2s + col);
            float2 q2 = *(const float2*)(T2d + 128 + col);
            acc_h[j][0] = bb.x + p1.x + q1.x;  acc_h[j][1] = bb.y + p1.y + q1.y;
            acc_h[j][2] = bb.x + p2.x + q2.x;  acc_h[j][3] = bb.y + p2.y + q2.y;
            float2 gb = *(const float2*)(bg + col);
            float2 u1 = *(const float2*)(T1s + 256 + col);
            float2 v1 = *(const float2*)(T1d + 384 + col);
            float2 u2 = *(const float2*)(T2s + 256 + col);
            float2 v2 = *(const float2*)(T2d + 384 + col);
            acc_g[j][0] = gb.x + u1.x + v1.x;  acc_g[j][1] = gb.y + u1.y + v1.y;
            acc_g[j][2] = gb.x + u2.x + v2.x;  acc_g[j][3] = gb.y + u2.y + v2.y;
        }

        // ---- GEMM1: h (B1 rows 0..127) and gate (rows 128..255), shared A frags ----
        #pragma unroll
        for (int s = 0; s < 8; s++) {
            int o0 = 32 * s + 4 * t;
            #pragma unroll
            for (int j = 0; j < 16; j++) {
                int n = j * 8 + g;
                mma3(acc_h[j], a1h[s], a1l[s], B1H, B1L, n, o0);
                mma3(acc_g[j], a1h[s], a1l[s], B1H, B1L, 128 + n, o0);
            }
        }

        // ---- LayerNorm(h) + GELU (exact erf), pack A2 frags ----
        float mu1, rs1, mu2, rs2;
        {
            float s1 = 0.f, q1 = 0.f, s2 = 0.f, q2 = 0.f;
            #pragma unroll
            for (int j = 0; j < 16; j++) {
                s1 += acc_h[j][0] + acc_h[j][1];
                q1 += acc_h[j][0] * acc_h[j][0] + acc_h[j][1] * acc_h[j][1];
                s2 += acc_h[j][2] + acc_h[j][3];
                q2 += acc_h[j][2] * acc_h[j][2] + acc_h[j][3] * acc_h[j][3];
            }
            #pragma unroll
            for (int o = 1; o <= 2; o <<= 1) {
                s1 += __shfl_xor_sync(0xFFFFFFFFu, s1, o);
                q1 += __shfl_xor_sync(0xFFFFFFFFu, q1, o);
                s2 += __shfl_xor_sync(0xFFFFFFFFu, s2, o);
                q2 += __shfl_xor_sync(0xFFFFFFFFu, q2, o);
            }
            mu1 = s1 * (1.f / 128.f); rs1 = rsqrtf(q1 * (1.f / 128.f) - mu1 * mu1 + EPSC);
            mu2 = s2 * (1.f / 128.f); rs2 = rsqrtf(q2 * (1.f / 128.f) - mu2 * mu2 + EPSC);
        }
        #pragma unroll
        for (int j = 0; j < 16; j++) {
            int col = j * 8 + 2 * t;
            float2 gv = *(const float2*)(g1 + col);
            float2 bv = *(const float2*)(be1 + col);
            float y0 = (acc_h[j][0] - mu1) * rs1 * gv.x + bv.x;
            float y1 = (acc_h[j][1] - mu1) * rs1 * gv.y + bv.y;
            float y2 = (acc_h[j][2] - mu2) * rs2 * gv.x + bv.x;
            float y3 = (acc_h[j][3] - mu2) * rs2 * gv.y + bv.y;
            acc_h[j][0] = 0.5f * y0 * (1.f + erff(y0 * SQRT1_2));
            acc_h[j][1] = 0.5f * y1 * (1.f + erff(y1 * SQRT1_2));
            acc_h[j][2] = 0.5f * y2 * (1.f + erff(y2 * SQRT1_2));
            acc_h[j][3] = 0.5f * y3 * (1.f + erff(y3 * SQRT1_2));
        }
        // A2 fragments come straight from the accumulator layout (j=2s+i)
        uint32_t a2h[8][4], a2l[8][4];
        #pragma unroll
        for (int s = 0; s < 8; s++) {
            split_pack(acc_h[2 * s][0],     acc_h[2 * s][1],     a2h[s][0], a2l[s][0]);
            split_pack(acc_h[2 * s][2],     acc_h[2 * s][3],     a2h[s][1], a2l[s][1]);
            split_pack(acc_h[2 * s + 1][0], acc_h[2 * s + 1][1], a2h[s][2], a2l[s][2]);
            split_pack(acc_h[2 * s + 1][2], acc_h[2 * s + 1][3], a2h[s][3], a2l[s][3]);
        }
        // sigmoid(gate) in place
        #pragma unroll
        for (int j = 0; j < 16; j++) {
            #pragma unroll
            for (int c = 0; c < 4; c++)
                acc_g[j][c] = 1.f / (1.f + expf(-acc_g[j][c]));
        }

        // ---- GEMM2: h @ W2 ----
        float acc2[16][4];
        #pragma unroll
        for (int j = 0; j < 16; j++)
            #pragma unroll
            for (int c = 0; c < 4; c++) acc2[j][c] = 0.f;
        #pragma unroll
        for (int s = 0; s < 8; s++) {
            int o0 = 32 * s + 4 * t;
            #pragma unroll
            for (int j = 0; j < 16; j++)
                mma3(acc2[j], a2h[s], a2l[s], W2H, W2L, j * 8 + g, o0);
        }

        // ---- combine: r = (h2 + b2) * gate + edge_attr ----
        #pragma unroll
        for (int j = 0; j < 16; j++) {
            int col = j * 8 + 2 * t;
            float2 bv = *(const float2*)(b2 + col);
            float2 eA = *(const float2*)(ea + (size_t)e1 * 128 + col);
            float2 eB = *(const float2*)(ea + (size_t)e2 * 128 + col);
            acc2[j][0] = (acc2[j][0] + bv.x) * acc_g[j][0] + eA.x;
            acc2[j][1] = (acc2[j][1] + bv.y) * acc_g[j][1] + eA.y;
            acc2[j][2] = (acc2[j][2] + bv.x) * acc_g[j][2] + eB.x;
            acc2[j][3] = (acc2[j][3] + bv.y) * acc_g[j][3] + eB.y;
        }
        // ---- final LayerNorm + store ----
        {
            float s1 = 0.f, q1 = 0.f, s2 = 0.f, q2 = 0.f;
            #pragma unroll
            for (int j = 0; j < 16; j++) {
                s1 += acc2[j][0] + acc2[j][1];
                q1 += acc2[j][0] * acc2[j][0] + acc2[j][1] * acc2[j][1];
                s2 += acc2[j][2] + acc2[j][3];
                q2 += acc2[j][2] * acc2[j][2] + acc2[j][3] * acc2[j][3];
            }
            #pragma unroll
            for (int o = 1; o <= 2; o <<= 1) {
                s1 += __shfl_xor_sync(0xFFFFFFFFu, s1, o);
                q1 += __shfl_xor_sync(0xFFFFFFFFu, q1, o);
                s2 += __shfl_xor_sync(0xFFFFFFFFu, s2, o);
                q2 += __shfl_xor_sync(0xFFFFFFFFu, q2, o);
            }
            float mu1f = s1 * (1.f / 128.f);
            float rs1f = rsqrtf(q1 * (1.f / 128.f) - mu1f * mu1f + EPSC);
            float mu2f = s2 * (1.f / 128.f);
            float rs2f = rsqrtf(q2 * (1.f / 128.f) - mu2f * mu2f + EPSC);
            #pragma unroll
            for (int j = 0; j < 16; j++) {
                int col = j * 8 + 2 * t;
                float2 gv = *(const float2*)(gn + col);
                float2 bv = *(const float2*)(bn + col);
                float2 o1, o2;
                o1.x = (acc2[j][0] - mu1f) * rs1f * gv.x + bv.x;
                o1.y = (acc2[j][1] - mu1f) * rs1f * gv.y + bv.y;
                o2.x = (acc2[j][2] - mu2f) * rs2f * gv.x + bv.x;
                o2.y = (acc2[j][3] - mu2f) * rs2f * gv.y + bv.y;
                *(float2*)(out + (size_t)e1 * 128 + col) = o1;
                *(float2*)(out + (size_t)e2 * 128 + col) = o2;
            }
        }
    }
}

// ---------------------------------------------------------------------------
extern "C" void kernel_launch(void* const* d_in, const int* in_sizes, int n_in,
                              void* d_out, int out_size)
{
    const float* x   = (const float*)d_in[0];
    const int*   ei  = (const int*)d_in[1];
    const float* ea  = (const float*)d_in[2];
    const float* W1  = (const float*)d_in[3];
    const float* b1  = (const float*)d_in[4];
    const float* g1  = (const float*)d_in[5];
    const float* be1 = (const float*)d_in[6];
    const float* W2  = (const float*)d_in[7];
    const float* b2  = (const float*)d_in[8];
    const float* Wg  = (const float*)d_in[9];
    const float* bg  = (const float*)d_in[10];
    const float* gn  = (const float*)d_in[11];
    const float* bn  = (const float*)d_in[12];
    float*       out = (float*)d_out;

    const int node_smem = 163840;
    const int edge_smem = 229376;
    cudaFuncSetAttribute(node_mma_kernel, cudaFuncAttributeMaxDynamicSharedMemorySize, node_smem);
    cudaFuncSetAttribute(edge_mma_kernel, cudaFuncAttributeMaxDynamicSharedMemorySize, edge_smem);

    node_mma_kernel<<<GRID_P, 256, node_smem>>>(x, W1, Wg);
    edge_mma_kernel<<<GRID_P, 256, edge_smem>>>(ei, ea, W1, b1, g1, be1,
                                                W2, b2, Wg, bg, gn, bn, out);
}

// round 6
// speedup vs baseline: 2.3378x; 1.0542x over previous
#include <cuda_runtime.h>
#include <cuda_bf16.h>
#include <stdint.h>
#include <math.h>

#define NN 100000
#define NE 524288
#define EPSC 1e-5f
#define EDGE_TILES 4096
#define NODE_TILES 782
#define GRID_P 148
#define SQRT1_2 0.70710678118654752440f

// g_T[n][0:128]=x@W1[0:128]  [128:256]=x@W1[128:256]  [256:384]=x@Wg[0:128]  [384:512]=x@Wg[128:256]
static __device__ float g_T[(size_t)NN * 512];

// Pre-split, pre-swizzled bf16 hi/lo weight images (built once by prep_kernel)
static __device__ char g_B1H_[65536], g_B1L_[65536];       // [W1e|Wge] 256n x 128k
static __device__ char g_W2H_[32768], g_W2L_[32768];       // W2 128n x 128k
static __device__ char g_BNH_[2][65536], g_BNL_[2][65536]; // node W1 / Wg, 256n x 128k

// ---------------- helpers ----------------
__device__ __forceinline__ int swb(int row, int b) {           // 256B rows, xor swizzle
    return row * 256 + (b ^ ((row & 7) << 4));
}
__device__ __forceinline__ int gofs(int row, int c) {          // gate fp32, 64 cols/row
    return row * 256 + ((c * 4) ^ ((row & 7) << 5));
}
__device__ __forceinline__ void split_pack(float a, float b, uint32_t& hi, uint32_t& lo) {
    __nv_bfloat16 ha = __float2bfloat16(a), hb = __float2bfloat16(b);
    __nv_bfloat162 h2 = __halves2bfloat162(ha, hb);
    hi = *reinterpret_cast<uint32_t*>(&h2);
    __nv_bfloat162 l2 = __floats2bfloat162_rn(a - __bfloat162float(ha), b - __bfloat162float(hb));
    lo = *reinterpret_cast<uint32_t*>(&l2);
}
__device__ __forceinline__ void mma16816(float* c, uint32_t a0, uint32_t a1, uint32_t a2,
                                         uint32_t a3, uint32_t b0, uint32_t b1) {
    asm volatile("mma.sync.aligned.m16n8k16.row.col.f32.bf16.bf16.f32 "
                 "{%0,%1,%2,%3}, {%4,%5,%6,%7}, {%8,%9}, {%0,%1,%2,%3};"
                 : "+f"(c[0]), "+f"(c[1]), "+f"(c[2]), "+f"(c[3])
                 : "r"(a0), "r"(a1), "r"(a2), "r"(a3), "r"(b0), "r"(b1));
}
__device__ __forceinline__ void mma3(float* acc, const uint32_t ah[4], const uint32_t al[4],
                                     const char* BH, const char* BL, int n, int o0) {
    uint32_t bh0 = *(const uint32_t*)(BH + swb(n, o0));
    uint32_t bh1 = *(const uint32_t*)(BH + swb(n, o0 + 16));
    uint32_t bl0 = *(const uint32_t*)(BL + swb(n, o0));
    uint32_t bl1 = *(const uint32_t*)(BL + swb(n, o0 + 16));
    mma16816(acc, ah[0], ah[1], ah[2], ah[3], bh0, bh1);
    mma16816(acc, al[0], al[1], al[2], al[3], bh0, bh1);
    mma16816(acc, ah[0], ah[1], ah[2], ah[3], bl0, bl1);
}
__device__ __forceinline__ void load_afrag(uint32_t f[4], const char* base, int lr, int o0) {
    f[0] = *(const uint32_t*)(base + swb(lr, o0));
    f[1] = *(const uint32_t*)(base + swb(lr + 8, o0));
    f[2] = *(const uint32_t*)(base + swb(lr, o0 + 16));
    f[3] = *(const uint32_t*)(base + swb(lr + 8, o0 + 16));
}

// ============================================================================
// Prep kernel: build split/swizzled bf16 hi/lo weight images. 448 x 256.
// ============================================================================
__global__ void prep_kernel(const float* __restrict__ W1,
                            const float* __restrict__ Wg,
                            const float* __restrict__ W2)
{
    int i = blockIdx.x * 256 + threadIdx.x;   // 0 .. 114687
    float v;
    char *dh, *dl;
    int o;
    if (i < 32768) {                           // B1 = [W1e | Wge]
        int n = i >> 7, k = i & 127;
        v = (n < 128) ? W1[(size_t)(256 + k) * 128 + n]
                      : Wg[(size_t)(256 + k) * 128 + (n - 128)];
        o = swb(n, 2 * k); dh = g_B1H_; dl = g_B1L_;
    } else if (i < 49152) {                    // W2
        int j = i - 32768;
        int n = j >> 7, k = j & 127;
        v = W2[(size_t)k * 128 + n];
        o = swb(n, 2 * k); dh = g_W2H_; dl = g_W2L_;
    } else {                                   // node weights, q = 0 (W1) / 1 (Wg)
        int j = i - 49152;
        int q = j >> 15; j &= 32767;
        int n = j >> 7, k = j & 127;
        const float* W = q ? Wg : W1;
        v = (n < 128) ? W[(size_t)k * 128 + n]
                      : W[(size_t)(128 + k) * 128 + (n - 128)];
        o = swb(n, 2 * k); dh = g_BNH_[q]; dl = g_BNL_[q];
    }
    __nv_bfloat16 h = __float2bfloat16(v);
    *(__nv_bfloat16*)(dh + o) = h;
    *(__nv_bfloat16*)(dl + o) = __float2bfloat16(v - __bfloat162float(h));
}

// ============================================================================
// Node kernel: persistent, streams A fragments, low register pressure.
// smem: BH 64K | BL 64K | AH 32K | AL 32K = 196608
// ============================================================================
__global__ __launch_bounds__(256, 1)
void node_mma_kernel(const float* __restrict__ x)
{
    extern __shared__ char sm[];
    char* BH = sm;
    char* BL = sm + 65536;
    char* AH = sm + 131072;
    char* AL = sm + 163840;

    const int tid = threadIdx.x;
    const int w = tid >> 5, lane = tid & 31;
    const int g = lane >> 2, t = lane & 3;
    const int lr = w * 16 + g;

    for (int q = 0; q < 2; q++) {
        __syncthreads();
        for (int i = tid; i < 4096; i += 256) {
            ((float4*)BH)[i] = ((const float4*)g_BNH_[q])[i];
            ((float4*)BL)[i] = ((const float4*)g_BNL_[q])[i];
        }
        __syncthreads();

        for (int tile = blockIdx.x; tile < NODE_TILES; tile += gridDim.x) {
            // stage this warp's own 16 rows of x (bf16 hi/lo)
            #pragma unroll
            for (int i = 0; i < 16; i++) {
                int r = w * 16 + i;
                int node = tile * 128 + r;
                float4 v = (node < NN) ? *(const float4*)(x + (size_t)node * 128 + lane * 4)
                                       : make_float4(0.f, 0.f, 0.f, 0.f);
                uint32_t h0, l0, h1, l1;
                split_pack(v.x, v.y, h0, l0);
                split_pack(v.z, v.w, h1, l1);
                int o = swb(r, 8 * lane);
                *(uint32_t*)(AH + o) = h0; *(uint32_t*)(AH + o + 4) = h1;
                *(uint32_t*)(AL + o) = l0; *(uint32_t*)(AL + o + 4) = l1;
            }
            __syncwarp();

            const int n1 = tile * 128 + w * 16 + g;
            const int n2 = n1 + 8;
            #pragma unroll
            for (int nh = 0; nh < 2; nh++) {
                float acc[16][4];
                #pragma unroll
                for (int j = 0; j < 16; j++)
                    #pragma unroll
                    for (int c = 0; c < 4; c++) acc[j][c] = 0.f;
                #pragma unroll
                for (int s = 0; s < 8; s++) {
                    int o0 = 32 * s + 4 * t;
                    uint32_t ah[4], al[4];
                    load_afrag(ah, AH, lr, o0);
                    load_afrag(al, AL, lr, o0);
                    #pragma unroll
                    for (int j = 0; j < 16; j++)
                        mma3(acc[j], ah, al, BH, BL, nh * 128 + j * 8 + g, o0);
                }
                float* b1p = g_T + (size_t)n1 * 512 + q * 256 + nh * 128;
                float* b2p = g_T + (size_t)n2 * 512 + q * 256 + nh * 128;
                #pragma unroll
                for (int j = 0; j < 16; j++) {
                    int col = j * 8 + 2 * t;
                    if (n1 < NN) *(float2*)(b1p + col) = make_float2(acc[j][0], acc[j][1]);
                    if (n2 < NN) *(float2*)(b2p + col) = make_float2(acc[j][2], acc[j][3]);
                }
            }
            __syncwarp();
        }
    }
}

// ============================================================================
// Edge kernel: persistent, 128 edges/tile, 8 warps x 16 rows (row-private A).
// smem: B1H 64K | B1L 64K | AH 32K | AL 32K | W2H 16K | W2L 16K = 229376
// A region is reused: A1 (bf16 hi/lo) -> gate (fp32, split cols 0..63 / 64..127)
// ============================================================================
__global__ __launch_bounds__(256, 1)
void edge_mma_kernel(const int* __restrict__ ei, const float* __restrict__ ea,
                     const float* __restrict__ b1, const float* __restrict__ g1,
                     const float* __restrict__ be1, const float* __restrict__ b2,
                     const float* __restrict__ bg, const float* __restrict__ gn,
                     const float* __restrict__ bn, float* __restrict__ out)
{
    extern __shared__ char sm[];
    char* B1H = sm;
    char* B1L = sm + 65536;
    char* AH  = sm + 131072;
    char* AL  = sm + 163840;
    char* W2H = sm + 196608;
    char* W2L = sm + 212992;

    const int tid = threadIdx.x;
    const int w = tid >> 5, lane = tid & 31;
    const int g = lane >> 2, t = lane & 3;
    const int lr = w * 16 + g;

    // copy persistent B1 image
    for (int i = tid; i < 4096; i += 256) {
        ((float4*)B1H)[i] = ((const float4*)g_B1H_)[i];
        ((float4*)B1L)[i] = ((const float4*)g_B1L_)[i];
    }
    __syncthreads();

    for (int tile = blockIdx.x; tile < EDGE_TILES; tile += gridDim.x) {
        // ---- stage this warp's own 16 rows of edge_attr (bf16 hi/lo) ----
        #pragma unroll
        for (int i = 0; i < 16; i++) {
            int r = w * 16 + i;
            float4 v = *(const float4*)(ea + (size_t)(tile * 128 + r) * 128 + lane * 4);
            uint32_t h0, l0, h1, l1;
            split_pack(v.x, v.y, h0, l0);
            split_pack(v.z, v.w, h1, l1);
            int o = swb(r, 8 * lane);
            *(uint32_t*)(AH + o) = h0; *(uint32_t*)(AH + o + 4) = h1;
            *(uint32_t*)(AL + o) = l0; *(uint32_t*)(AL + o + 4) = l1;
        }
        __syncwarp();

        // ---- gathers + biases init accumulators (fp32 exact) ----
        const int e1 = tile * 128 + w * 16 + g;
        const int e2 = e1 + 8;
        const int is1 = ei[e1], id1 = ei[NE + e1];
        const int is2 = ei[e2], id2 = ei[NE + e2];
        const float* T1s = g_T + (size_t)is1 * 512;
        const float* T1d = g_T + (size_t)id1 * 512;
        const float* T2s = g_T + (size_t)is2 * 512;
        const float* T2d = g_T + (size_t)id2 * 512;

        float acc_h[16][4], acc_g[16][4];
        #pragma unroll
        for (int j = 0; j < 16; j++) {
            int col = j * 8 + 2 * t;
            float2 bb = *(const float2*)(b1 + col);
            float2 p1 = *(const float2*)(T1s + col);
            float2 q1 = *(const float2*)(T1d + 128 + col);
            float2 p2 = *(const float2*)(T2s + col);
            float2 q2 = *(const float2*)(T2d + 128 + col);
            acc_h[j][0] = bb.x + p1.x + q1.x;  acc_h[j][1] = bb.y + p1.y + q1.y;
            acc_h[j][2] = bb.x + p2.x + q2.x;  acc_h[j][3] = bb.y + p2.y + q2.y;
            float2 gb = *(const float2*)(bg + col);
            float2 u1 = *(const float2*)(T1s + 256 + col);
            float2 v1 = *(const float2*)(T1d + 384 + col);
            float2 u2 = *(const float2*)(T2s + 256 + col);
            float2 v2 = *(const float2*)(T2d + 384 + col);
            acc_g[j][0] = gb.x + u1.x + v1.x;  acc_g[j][1] = gb.y + u1.y + v1.y;
            acc_g[j][2] = gb.x + u2.x + v2.x;  acc_g[j][3] = gb.y + u2.y + v2.y;
        }

        // ---- GEMM1: stream A frags per k-chunk; h and gate share them ----
        #pragma unroll
        for (int s = 0; s < 8; s++) {
            int o0 = 32 * s + 4 * t;
            uint32_t ah[4], al[4];
            load_afrag(ah, AH, lr, o0);
            load_afrag(al, AL, lr, o0);
            #pragma unroll
            for (int j = 0; j < 16; j++) {
                int n = j * 8 + g;
                mma3(acc_h[j], ah, al, B1H, B1L, n, o0);
                mma3(acc_g[j], ah, al, B1H, B1L, 128 + n, o0);
            }
        }

        // ---- LayerNorm(h) + exact GELU -> a2 fragments in registers ----
        float mu1, rs1, mu2, rs2;
        {
            float s1 = 0.f, q1 = 0.f, s2 = 0.f, q2 = 0.f;
            #pragma unroll
            for (int j = 0; j < 16; j++) {
                s1 += acc_h[j][0] + acc_h[j][1];
                q1 += acc_h[j][0] * acc_h[j][0] + acc_h[j][1] * acc_h[j][1];
                s2 += acc_h[j][2] + acc_h[j][3];
                q2 += acc_h[j][2] * acc_h[j][2] + acc_h[j][3] * acc_h[j][3];
            }
            #pragma unroll
            for (int o = 1; o <= 2; o <<= 1) {
                s1 += __shfl_xor_sync(0xFFFFFFFFu, s1, o);
                q1 += __shfl_xor_sync(0xFFFFFFFFu, q1, o);
                s2 += __shfl_xor_sync(0xFFFFFFFFu, s2, o);
                q2 += __shfl_xor_sync(0xFFFFFFFFu, q2, o);
            }
            mu1 = s1 * (1.f / 128.f); rs1 = rsqrtf(q1 * (1.f / 128.f) - mu1 * mu1 + EPSC);
            mu2 = s2 * (1.f / 128.f); rs2 = rsqrtf(q2 * (1.f / 128.f) - mu2 * mu2 + EPSC);
        }
        uint32_t a2h[8][4], a2l[8][4];
        #pragma unroll
        for (int j = 0; j < 16; j++) {
            int col = j * 8 + 2 * t;
            float2 gv = *(const float2*)(g1 + col);
            float2 bv = *(const float2*)(be1 + col);
            float y0 = (acc_h[j][0] - mu1) * rs1 * gv.x + bv.x;
            float y1 = (acc_h[j][1] - mu1) * rs1 * gv.y + bv.y;
            float y2 = (acc_h[j][2] - mu2) * rs2 * gv.x + bv.x;
            float y3 = (acc_h[j][3] - mu2) * rs2 * gv.y + bv.y;
            y0 = 0.5f * y0 * (1.f + erff(y0 * SQRT1_2));
            y1 = 0.5f * y1 * (1.f + erff(y1 * SQRT1_2));
            y2 = 0.5f * y2 * (1.f + erff(y2 * SQRT1_2));
            y3 = 0.5f * y3 * (1.f + erff(y3 * SQRT1_2));
            int s = j >> 1, i = j & 1;
            split_pack(y0, y1, a2h[s][2 * i],     a2l[s][2 * i]);
            split_pack(y2, y3, a2h[s][2 * i + 1], a2l[s][2 * i + 1]);
        }

        // ---- sigmoid(gate) -> smem (own rows; A1 region is dead now) ----
        #pragma unroll
        for (int j = 0; j < 16; j++) {
            int col = j * 8 + 2 * t;
            int cl = col & 63;
            char* gb = (col < 64) ? AH : AL;
            float s0 = 1.f / (1.f + expf(-acc_g[j][0]));
            float s1 = 1.f / (1.f + expf(-acc_g[j][1]));
            float s2 = 1.f / (1.f + expf(-acc_g[j][2]));
            float s3 = 1.f / (1.f + expf(-acc_g[j][3]));
            *(float2*)(gb + gofs(w * 16 + g, cl))     = make_float2(s0, s1);
            *(float2*)(gb + gofs(w * 16 + g + 8, cl)) = make_float2(s2, s3);
        }

        // ---- GEMM2: h @ W2, W2 staged in two n-halves ----
        float acc2[16][4];
        #pragma unroll
        for (int j = 0; j < 16; j++)
            #pragma unroll
            for (int c = 0; c < 4; c++) acc2[j][c] = 0.f;
        #pragma unroll
        for (int nh = 0; nh < 2; nh++) {
            __syncthreads();   // all warps done reading previous W2 half
            for (int i = tid; i < 1024; i += 256) {
                ((float4*)W2H)[i] = ((const float4*)(g_W2H_ + nh * 16384))[i];
                ((float4*)W2L)[i] = ((const float4*)(g_W2L_ + nh * 16384))[i];
            }
            __syncthreads();
            #pragma unroll
            for (int s = 0; s < 8; s++) {
                int o0 = 32 * s + 4 * t;
                #pragma unroll
                for (int jl = 0; jl < 8; jl++)
                    mma3(acc2[nh * 8 + jl], a2h[s], a2l[s], W2H, W2L, jl * 8 + g, o0);
            }
        }

        // ---- combine: r = (h2 + b2) * gate + edge_attr ----
        #pragma unroll
        for (int j = 0; j < 16; j++) {
            int col = j * 8 + 2 * t;
            int cl = col & 63;
            const char* gb = (col < 64) ? AH : AL;
            float2 gA = *(const float2*)(gb + gofs(w * 16 + g, cl));
            float2 gB = *(const float2*)(gb + gofs(w * 16 + g + 8, cl));
            float2 bv = *(const float2*)(b2 + col);
            float2 eA = *(const float2*)(ea + (size_t)e1 * 128 + col);
            float2 eB = *(const float2*)(ea + (size_t)e2 * 128 + col);
            acc2[j][0] = (acc2[j][0] + bv.x) * gA.x + eA.x;
            acc2[j][1] = (acc2[j][1] + bv.y) * gA.y + eA.y;
            acc2[j][2] = (acc2[j][2] + bv.x) * gB.x + eB.x;
            acc2[j][3] = (acc2[j][3] + bv.y) * gB.y + eB.y;
        }

        // ---- final LayerNorm + store ----
        {
            float s1 = 0.f, q1 = 0.f, s2 = 0.f, q2 = 0.f;
            #pragma unroll
            for (int j = 0; j < 16; j++) {
                s1 += acc2[j][0] + acc2[j][1];
                q1 += acc2[j][0] * acc2[j][0] + acc2[j][1] * acc2[j][1];
                s2 += acc2[j][2] + acc2[j][3];
                q2 += acc2[j][2] * acc2[j][2] + acc2[j][3] * acc2[j][3];
            }
            #pragma unroll
            for (int o = 1; o <= 2; o <<= 1) {
                s1 += __shfl_xor_sync(0xFFFFFFFFu, s1, o);
                q1 += __shfl_xor_sync(0xFFFFFFFFu, q1, o);
                s2 += __shfl_xor_sync(0xFFFFFFFFu, s2, o);
                q2 += __shfl_xor_sync(0xFFFFFFFFu, q2, o);
            }
            float mu1f = s1 * (1.f / 128.f);
            float rs1f = rsqrtf(q1 * (1.f / 128.f) - mu1f * mu1f + EPSC);
            float mu2f = s2 * (1.f / 128.f);
            float rs2f = rsqrtf(q2 * (1.f / 128.f) - mu2f * mu2f + EPSC);
            #pragma unroll
            for (int j = 0; j < 16; j++) {
                int col = j * 8 + 2 * t;
                float2 gv = *(const float2*)(gn + col);
                float2 bv = *(const float2*)(bn + col);
                float2 o1, o2;
                o1.x = (acc2[j][0] - mu1f) * rs1f * gv.x + bv.x;
                o1.y = (acc2[j][1] - mu1f) * rs1f * gv.y + bv.y;
                o2.x = (acc2[j][2] - mu2f) * rs2f * gv.x + bv.x;
                o2.y = (acc2[j][3] - mu2f) * rs2f * gv.y + bv.y;
                *(float2*)(out + (size_t)e1 * 128 + col) = o1;
                *(float2*)(out + (size_t)e2 * 128 + col) = o2;
            }
        }
    }
}

// ---------------------------------------------------------------------------
extern "C" void kernel_launch(void* const* d_in, const int* in_sizes, int n_in,
                              void* d_out, int out_size)
{
    const float* x   = (const float*)d_in[0];
    const int*   ei  = (const int*)d_in[1];
    const float* ea  = (const float*)d_in[2];
    const float* W1  = (const float*)d_in[3];
    const float* b1  = (const float*)d_in[4];
    const float* g1  = (const float*)d_in[5];
    const float* be1 = (const float*)d_in[6];
    const float* W2  = (const float*)d_in[7];
    const float* b2  = (const float*)d_in[8];
    const float* Wg  = (const float*)d_in[9];
    const float* bg  = (const float*)d_in[10];
    const float* gn  = (const float*)d_in[11];
    const float* bn  = (const float*)d_in[12];
    float*       out = (float*)d_out;

    const int node_smem = 196608;
    const int edge_smem = 229376;
    cudaFuncSetAttribute(node_mma_kernel, cudaFuncAttributeMaxDynamicSharedMemorySize, node_smem);
    cudaFuncSetAttribute(edge_mma_kernel, cudaFuncAttributeMaxDynamicSharedMemorySize, edge_smem);

    prep_kernel<<<448, 256>>>(W1, Wg, W2);
    node_mma_kernel<<<GRID_P, 256, node_smem>>>(x);
    edge_mma_kernel<<<GRID_P, 256, edge_smem>>>(ei, ea, b1, g1, be1, b2, bg, gn, bn, out);
}